// round 17
// baseline (speedup 1.0000x reference)
#include <cuda_runtime.h>
#include <cuda_fp16.h>
#include <math.h>
#include <stdint.h>

#define BATCH 4
#define NQ 2048
#define NK 2048
#define DM 1024
#define NH 16
#define HD 64
#define MROWS (BATCH * NQ)   // 8192

// Scratch (all 16-bit)
__device__ __half g_Qh[MROWS * DM];
__device__ __half g_Kh[MROWS * DM];
__device__ __half g_Vh[MROWS * DM];
__device__ __half g_Oh[MROWS * DM];
__device__ __half g_WTH[4 * DM * DM];
__device__ __half g_INH[3 * MROWS * DM];

#define QSCALE (0.03125f * 1.4426950408889634f)   // 1/sqrt(1024) * log2(e)

__device__ __forceinline__ float ex2(float x) {
    float r;
    asm("ex2.approx.ftz.f32 %0, %1;" : "=f"(r) : "f"(x));
    return r;
}

__device__ __forceinline__ void mma_f16(float* c, const uint32_t* a, const uint32_t* b) {
    asm volatile(
        "mma.sync.aligned.m16n8k16.row.col.f32.f16.f16.f32 "
        "{%0,%1,%2,%3}, {%4,%5,%6,%7}, {%8,%9}, {%0,%1,%2,%3};"
        : "+f"(c[0]), "+f"(c[1]), "+f"(c[2]), "+f"(c[3])
        : "r"(a[0]), "r"(a[1]), "r"(a[2]), "r"(a[3]), "r"(b[0]), "r"(b[1]));
}

__device__ __forceinline__ void ldsm_x4(uint32_t& r0, uint32_t& r1,
                                        uint32_t& r2, uint32_t& r3, uint32_t addr) {
    asm volatile("ldmatrix.sync.aligned.m8n8.x4.shared.b16 {%0,%1,%2,%3}, [%4];"
        : "=r"(r0), "=r"(r1), "=r"(r2), "=r"(r3) : "r"(addr));
}

__device__ __forceinline__ void ldsm_x4_trans(uint32_t& r0, uint32_t& r1,
                                              uint32_t& r2, uint32_t& r3, uint32_t addr) {
    asm volatile("ldmatrix.sync.aligned.m8n8.x4.trans.shared.b16 {%0,%1,%2,%3}, [%4];"
        : "=r"(r0), "=r"(r1), "=r"(r2), "=r"(r3) : "r"(addr));
}

__device__ __forceinline__ uint32_t smem_u32(const void* p) {
    uint32_t a;
    asm("{ .reg .u64 t; cvta.to.shared.u64 t, %1; cvt.u32.u64 %0, t; }"
        : "=r"(a) : "l"(p));
    return a;
}

__device__ __forceinline__ void cp16(uint32_t dst, const void* src) {
    asm volatile("cp.async.ca.shared.global [%0], [%1], 16;" :: "r"(dst), "l"(src));
}
#define CP_COMMIT() asm volatile("cp.async.commit_group;" ::: "memory")
#define CP_WAIT(n)  asm volatile("cp.async.wait_group %0;" :: "n"(n) : "memory")

// ---------------------------------------------------------------------------
// Weight transpose: all 4 weights -> fp16 transposed [N][K]
// ---------------------------------------------------------------------------
__global__ void transpose4(const float* __restrict__ W0, const float* __restrict__ W1,
                           const float* __restrict__ W2, const float* __restrict__ W3,
                           __half* __restrict__ WTH)
{
    __shared__ float t[32][33];
    const int z = blockIdx.z;
    const float* W = (z == 0) ? W0 : (z == 1) ? W1 : (z == 2) ? W2 : W3;
    __half* d = WTH + (size_t)z * DM * DM;
    int bx = blockIdx.x * 32, by = blockIdx.y * 32;
    for (int j = threadIdx.y; j < 32; j += 8)
        t[j][threadIdx.x] = W[(size_t)(by + j) * DM + bx + threadIdx.x];
    __syncthreads();
    for (int j = threadIdx.y; j < 32; j += 8)
        d[(size_t)(bx + j) * DM + by + threadIdx.x] = __float2half_rn(t[threadIdx.x][j]);
}

// ---------------------------------------------------------------------------
// Input prep: all 3 activations -> fp16
// ---------------------------------------------------------------------------
__global__ __launch_bounds__(256) void prep_inputs(
    const float* __restrict__ q, const float* __restrict__ k,
    const float* __restrict__ v, __half* __restrict__ INH)
{
    const int z = blockIdx.z;
    const float* src = (z == 0) ? q : (z == 1) ? k : v;
    __half* d = INH + (size_t)z * MROWS * DM;
    const size_t n4 = (size_t)MROWS * DM / 4;
    for (size_t i = blockIdx.x * 256 + threadIdx.x; i < n4; i += (size_t)gridDim.x * 256) {
        float4 x = ((const float4*)src)[i];
        __half2 lo = __floats2half2_rn(x.x, x.y);
        __half2 hi = __floats2half2_rn(x.z, x.w);
        uint2 pk;
        pk.x = *(uint32_t*)&lo;
        pk.y = *(uint32_t*)&hi;
        ((uint2*)d)[i] = pk;
    }
}

// ---------------------------------------------------------------------------
// FP16 mma GEMM (unchanged from R16): m16n8k16, 128x128, BK=64.
// mode: 0 = fp16; 1 = fp16 * QSCALE; 2 = fp32 + bias.
// ---------------------------------------------------------------------------
#define GBM 128
#define GBN 128
#define GBK 64
#define HST 36
#define HTILE_U32 (GBM * HST)
#define HSTAGE_U32 (2 * HTILE_U32)
#define SMEM_GEMMH (2 * HSTAGE_U32 * 4)

__device__ __forceinline__ void gemmh_stage_issue(
    const __half* __restrict__ A, const __half* __restrict__ BT,
    int bm, int bn, int k0, uint32_t sA_addr, uint32_t sB_addr, int tid)
{
#pragma unroll
    for (int i = 0; i < 4; i++) {
        int idx = tid + i * 256;
        int r = idx >> 3;
        int c = idx & 7;
        uint32_t off = (uint32_t)(r * HST * 4 + c * 16);
        cp16(sA_addr + off, A + (size_t)(bm + r) * DM + k0 + c * 8);
        cp16(sB_addr + off, BT + (size_t)(bn + r) * DM + k0 + c * 8);
    }
    CP_COMMIT();
}

__device__ __forceinline__ void gemm16_core(
    const __half* __restrict__ A, const __half* __restrict__ BT,
    const float* __restrict__ bias, void* __restrict__ Cv,
    int mode, uint32_t* hsm)
{
    const uint32_t sbase = smem_u32(hsm);
    const int tid = threadIdx.x;
    const int wid = tid >> 5;
    const int lane = tid & 31;
    const int gID = lane >> 2;
    const int ig  = lane & 3;
    const int lm_m = lane >> 3;
    const int lm_r = lane & 7;
    const int warp_m = wid >> 2;
    const int warp_n = wid & 3;
    const int bm = blockIdx.y * GBM;
    const int bn = blockIdx.x * GBN;

    float acc[4][4][4];
#pragma unroll
    for (int i = 0; i < 4; i++)
#pragma unroll
        for (int j = 0; j < 4; j++)
#pragma unroll
            for (int v = 0; v < 4; v++) acc[i][j][v] = 0.0f;

    const int kSteps = DM / GBK;   // 16

    gemmh_stage_issue(A, BT, bm, bn, 0, sbase, sbase + HTILE_U32 * 4, tid);

    for (int kt = 0; kt < kSteps; kt++) {
        const int cur = kt & 1;
        if (kt + 1 < kSteps) {
            const int nxt = (kt + 1) & 1;
            gemmh_stage_issue(A, BT, bm, bn, (kt + 1) * GBK,
                              sbase + nxt * HSTAGE_U32 * 4,
                              sbase + (nxt * HSTAGE_U32 + HTILE_U32) * 4, tid);
            CP_WAIT(1);
        } else {
            CP_WAIT(0);
        }
        __syncthreads();

        const uint32_t sAa = sbase + (uint32_t)(cur * HSTAGE_U32 * 4);
        const uint32_t sBa = sAa + HTILE_U32 * 4;

#pragma unroll
        for (int st = 0; st < 4; st++) {
            uint32_t afrag[4][4];
#pragma unroll
            for (int mt = 0; mt < 4; mt++) {
                uint32_t addr = sAa + (uint32_t)(
                    ((warp_m * 64 + mt * 16 + (lm_m & 1) * 8 + lm_r) * HST
                     + st * 8 + (lm_m >> 1) * 4) * 4);
                ldsm_x4(afrag[mt][0], afrag[mt][1], afrag[mt][2], afrag[mt][3], addr);
            }
            uint32_t bfrag[4][2];
#pragma unroll
            for (int p = 0; p < 2; p++) {
                uint32_t addr = sBa + (uint32_t)(
                    ((warp_n * 32 + p * 16 + (lm_m >> 1) * 8 + lm_r) * HST
                     + st * 8 + (lm_m & 1) * 4) * 4);
                ldsm_x4(bfrag[2*p][0], bfrag[2*p][1],
                        bfrag[2*p+1][0], bfrag[2*p+1][1], addr);
            }
#pragma unroll
            for (int mt = 0; mt < 4; mt++)
#pragma unroll
                for (int nt = 0; nt < 4; nt++)
                    mma_f16(acc[mt][nt], afrag[mt], bfrag[nt]);
        }
        __syncthreads();
    }

#pragma unroll
    for (int mt = 0; mt < 4; mt++) {
#pragma unroll
        for (int nt = 0; nt < 4; nt++) {
            int row = bm + warp_m * 64 + mt * 16 + gID;
            int col = bn + warp_n * 32 + nt * 8 + ig * 2;
            float2 v0, v1;
            v0.x = acc[mt][nt][0]; v0.y = acc[mt][nt][1];
            v1.x = acc[mt][nt][2]; v1.y = acc[mt][nt][3];
            if (mode == 2) {
                float b0 = bias[col], b1 = bias[col + 1];
                v0.x += b0; v0.y += b1;
                v1.x += b0; v1.y += b1;
                float* C = (float*)Cv;
                *(float2*)&C[(size_t)row * DM + col] = v0;
                *(float2*)&C[(size_t)(row + 8) * DM + col] = v1;
            } else {
                if (mode == 1) {
                    v0.x *= QSCALE; v0.y *= QSCALE;
                    v1.x *= QSCALE; v1.y *= QSCALE;
                }
                __half* C = (__half*)Cv;
                *(__half2*)&C[(size_t)row * DM + col] = __floats2half2_rn(v0.x, v0.y);
                *(__half2*)&C[(size_t)(row + 8) * DM + col] = __floats2half2_rn(v1.x, v1.y);
            }
        }
    }
}

__global__ __launch_bounds__(256, 2) void gemm_qkv(
    const __half* __restrict__ INH, const __half* __restrict__ WTH,
    __half* __restrict__ Qo, __half* __restrict__ Ko, __half* __restrict__ Vo)
{
    extern __shared__ uint32_t hsm[];
    const int z = blockIdx.z;
    const __half* A  = INH + (size_t)z * MROWS * DM;
    const __half* BT = WTH + (size_t)z * DM * DM;
    if (z == 0)      gemm16_core(A, BT, nullptr, Qo, 1, hsm);
    else if (z == 1) gemm16_core(A, BT, nullptr, Ko, 0, hsm);
    else             gemm16_core(A, BT, nullptr, Vo, 0, hsm);
}

__global__ __launch_bounds__(256, 2) void gemm_out16(
    const __half* __restrict__ A, const __half* __restrict__ BT,
    const float* __restrict__ bias, float* __restrict__ C)
{
    extern __shared__ uint32_t hsm[];
    gemm16_core(A, BT, bias, C, 2, hsm);
}

// ---------------------------------------------------------------------------
// Flash attention rev 6: all-fp16 MMA, P in registers, 128-key staged buffers
// (two 64-key compute halves per barrier), warp-vote rescale fast path.
// ---------------------------------------------------------------------------
#define QROWS 128
#define KSTH 72
#define VSTH 72
#define KTILE 128                    // staged keys per buffer
#define SK_H (KTILE * KSTH)
#define SV_H (KTILE * VSTH)
#define SMEM_ATT ((2 * SK_H + 2 * SV_H) * 2)   // 73728 B

__device__ __forceinline__ void attn_stage_issue(
    const __half* __restrict__ Kh, const __half* __restrict__ Vp,
    int b, int h, int kt, uint32_t sK_addr, uint32_t sV_addr, int tid)
{
    const __half* Kbase = Kh + ((size_t)b * NK + kt * KTILE) * DM + h * HD;
    const __half* Vbase = Vp + ((size_t)b * NK + kt * KTILE) * DM + h * HD;
#pragma unroll
    for (int i = 0; i < 4; i++) {
        int idx = tid + i * 256;
        int r = idx >> 3;       // 0..127
        int c16 = idx & 7;      // 0..7
        cp16(sK_addr + (uint32_t)(r * KSTH * 2 + c16 * 16),
             Kbase + (size_t)r * DM + c16 * 8);
        cp16(sV_addr + (uint32_t)(r * VSTH * 2 + c16 * 16),
             Vbase + (size_t)r * DM + c16 * 8);
    }
    CP_COMMIT();
}

__global__ __launch_bounds__(256, 2) void attn_mma(
    const __half* __restrict__ Qh, const __half* __restrict__ Kh,
    const __half* __restrict__ Vp, __half* __restrict__ Oh)
{
    extern __shared__ __half smh[];
    __half* sV = smh;
    __half* sK = sV + 2 * SV_H;
    const uint32_t sVa = smem_u32(sV);
    const uint32_t sKa = smem_u32(sK);

    const int tid = threadIdx.x;
    const int wid = tid >> 5;
    const int lane = tid & 31;
    const int gID = lane >> 2;
    const int ig  = lane & 3;
    const int lm_m = lane >> 3;
    const int lm_r = lane & 7;
    const int qt = blockIdx.x;
    const int h  = blockIdx.y;
    const int b  = blockIdx.z;

    const int r0 = wid * 16 + gID;

    attn_stage_issue(Kh, Vp, b, h, 0, sKa, sVa, tid);

    uint32_t qf[4][4];
    {
        const __half* Qb = Qh + ((size_t)b * NQ + qt * QROWS + r0) * DM + h * HD;
#pragma unroll
        for (int st = 0; st < 4; st++) {
            int kk0 = st * 16;
            qf[st][0] = *(const uint32_t*)&Qb[kk0 + 2 * ig];
            qf[st][1] = *(const uint32_t*)&Qb[8 * DM + kk0 + 2 * ig];
            qf[st][2] = *(const uint32_t*)&Qb[kk0 + 8 + 2 * ig];
            qf[st][3] = *(const uint32_t*)&Qb[8 * DM + kk0 + 8 + 2 * ig];
        }
    }

    const uint32_t k_rowoff = (uint32_t)((lm_m >> 1) * 8 + lm_r);
    const uint32_t k_coloff = (uint32_t)((lm_m & 1) * 8);
    const uint32_t v_rowoff = (uint32_t)((lm_m & 1) * 8 + lm_r);
    const uint32_t v_coloff = (uint32_t)((lm_m >> 1) * 8);

    float m0 = -1e30f, m1 = -1e30f, l0 = 0.0f, l1 = 0.0f;
    float oacc[8][4];
#pragma unroll
    for (int nt = 0; nt < 8; nt++)
#pragma unroll
        for (int v = 0; v < 4; v++) oacc[nt][v] = 0.0f;

    const int nTiles = NK / KTILE;   // 16
    for (int kt = 0; kt < nTiles; kt++) {
        const int cur = kt & 1;
        CP_WAIT(0);
        __syncthreads();
        if (kt + 1 < nTiles) {
            const int nxt = (kt + 1) & 1;
            attn_stage_issue(Kh, Vp, b, h, kt + 1,
                             sKa + nxt * SK_H * 2, sVa + nxt * SV_H * 2, tid);
        }

#pragma unroll
        for (int half = 0; half < 2; half++) {
            const uint32_t cKa = sKa + (uint32_t)(cur * SK_H * 2)
                                 + (uint32_t)(half * 64 * KSTH * 2);
            const uint32_t cVa = sVa + (uint32_t)(cur * SV_H * 2)
                                 + (uint32_t)(half * 64 * VSTH * 2);

            // ---- S = Q @ K^T (fp16) ----
            float s[8][4];
#pragma unroll
            for (int nt = 0; nt < 8; nt++)
#pragma unroll
                for (int v = 0; v < 4; v++) s[nt][v] = 0.0f;

#pragma unroll
            for (int st = 0; st < 4; st++) {
#pragma unroll
                for (int p = 0; p < 4; p++) {
                    uint32_t addr = cKa + (uint32_t)(
                        ((p * 16 + k_rowoff) * KSTH + st * 16 + k_coloff) * 2);
                    uint32_t b0, b1, b2, b3;
                    ldsm_x4(b0, b1, b2, b3, addr);
                    uint32_t bb0[2] = {b0, b1};
                    uint32_t bb1[2] = {b2, b3};
                    mma_f16(s[2*p],     qf[st], bb0);
                    mma_f16(s[2*p + 1], qf[st], bb1);
                }
            }

            // ---- Online softmax; P packed into A-frag registers ----
            float mt0 = -1e30f, mt1 = -1e30f;
#pragma unroll
            for (int nt = 0; nt < 8; nt++) {
                mt0 = fmaxf(mt0, fmaxf(s[nt][0], s[nt][1]));
                mt1 = fmaxf(mt1, fmaxf(s[nt][2], s[nt][3]));
            }
            mt0 = fmaxf(mt0, __shfl_xor_sync(0xffffffffu, mt0, 1));
            mt0 = fmaxf(mt0, __shfl_xor_sync(0xffffffffu, mt0, 2));
            mt1 = fmaxf(mt1, __shfl_xor_sync(0xffffffffu, mt1, 1));
            mt1 = fmaxf(mt1, __shfl_xor_sync(0xffffffffu, mt1, 2));

            float mn0 = fmaxf(m0, mt0), mn1 = fmaxf(m1, mt1);
            float a0 = ex2(m0 - mn0), a1 = ex2(m1 - mn1);
            m0 = mn0; m1 = mn1;

            uint32_t pf[8][2];
            float rs0 = 0.0f, rs1 = 0.0f;
#pragma unroll
            for (int nt = 0; nt < 8; nt++) {
                float p00 = ex2(s[nt][0] - mn0);
                float p01 = ex2(s[nt][1] - mn0);
                float p10 = ex2(s[nt][2] - mn1);
                float p11 = ex2(s[nt][3] - mn1);
                rs0 += p00 + p01;
                rs1 += p10 + p11;
                __half2 h0 = __floats2half2_rn(p00, p01);
                __half2 h1 = __floats2half2_rn(p10, p11);
                pf[nt][0] = *(uint32_t*)&h0;
                pf[nt][1] = *(uint32_t*)&h1;
            }
            rs0 += __shfl_xor_sync(0xffffffffu, rs0, 1);
            rs0 += __shfl_xor_sync(0xffffffffu, rs0, 2);
            rs1 += __shfl_xor_sync(0xffffffffu, rs1, 1);
            rs1 += __shfl_xor_sync(0xffffffffu, rs1, 2);
            l0 = l0 * a0 + rs0;
            l1 = l1 * a1 + rs1;

            // Warp-vote fast path: rescale almost never needed (tiny logits)
            if (!__all_sync(0xffffffffu, (a0 == 1.0f) && (a1 == 1.0f))) {
#pragma unroll
                for (int nt = 0; nt < 8; nt++) {
                    oacc[nt][0] *= a0; oacc[nt][1] *= a0;
                    oacc[nt][2] *= a1; oacc[nt][3] *= a1;
                }
            }

            // ---- oacc += P @ V (fp16; A-frags in regs, V ldmatrix.trans) ----
#pragma unroll
            for (int st = 0; st < 4; st++) {
                const int k0 = st * 16;
                uint32_t af[4];
                af[0] = pf[2*st][0];
                af[1] = pf[2*st][1];
                af[2] = pf[2*st + 1][0];
                af[3] = pf[2*st + 1][1];
#pragma unroll
                for (int p = 0; p < 4; p++) {
                    uint32_t addr = cVa + (uint32_t)(
                        ((k0 + v_rowoff) * VSTH + p * 16 + v_coloff) * 2);
                    uint32_t b0, b1, b2, b3;
                    ldsm_x4_trans(b0, b1, b2, b3, addr);
                    uint32_t bb0[2] = {b0, b1};
                    uint32_t bb1[2] = {b2, b3};
                    mma_f16(oacc[2*p],     af, bb0);
                    mma_f16(oacc[2*p + 1], af, bb1);
                }
            }
        }
    }

    // ---- Epilogue ----
    float inv0 = 1.0f / l0, inv1 = 1.0f / l1;
    const int grow = qt * QROWS + r0;
#pragma unroll
    for (int nt = 0; nt < 8; nt++) {
        int col = h * HD + nt * 8 + ig * 2;
        *(__half2*)&Oh[((size_t)b * NQ + grow) * DM + col] =
            __floats2half2_rn(oacc[nt][0] * inv0, oacc[nt][1] * inv0);
        *(__half2*)&Oh[((size_t)b * NQ + grow + 8) * DM + col] =
            __floats2half2_rn(oacc[nt][2] * inv1, oacc[nt][3] * inv1);
    }
}

// ---------------------------------------------------------------------------
// Launch
// ---------------------------------------------------------------------------
extern "C" void kernel_launch(void* const* d_in, const int* in_sizes, int n_in,
                              void* d_out, int out_size)
{
    const float* queries = (const float*)d_in[0];
    const float* keys    = (const float*)d_in[1];
    const float* values  = (const float*)d_in[2];
    const float* Wq      = (const float*)d_in[3];
    const float* Wk      = (const float*)d_in[4];
    const float* Wv      = (const float*)d_in[5];
    const float* Wo      = (const float*)d_in[6];
    const float* bo      = (const float*)d_in[7];
    float* out           = (float*)d_out;

    __half *Qh, *Kh, *Vh, *Oh, *WTH, *INH;
    cudaGetSymbolAddress((void**)&Qh, g_Qh);
    cudaGetSymbolAddress((void**)&Kh, g_Kh);
    cudaGetSymbolAddress((void**)&Vh, g_Vh);
    cudaGetSymbolAddress((void**)&Oh, g_Oh);
    cudaGetSymbolAddress((void**)&WTH, g_WTH);
    cudaGetSymbolAddress((void**)&INH, g_INH);

    static bool attr_set = false;
    if (!attr_set) {
        cudaFuncSetAttribute(attn_mma,
                             cudaFuncAttributeMaxDynamicSharedMemorySize, SMEM_ATT);
        cudaFuncSetAttribute(gemm_qkv,
                             cudaFuncAttributeMaxDynamicSharedMemorySize, SMEM_GEMMH);
        cudaFuncSetAttribute(gemm_out16,
                             cudaFuncAttributeMaxDynamicSharedMemorySize, SMEM_GEMMH);
        attr_set = true;
    }

    dim3 tgrid(DM / 32, DM / 32, 4), tblk(32, 8);
    transpose4<<<tgrid, tblk>>>(Wq, Wk, Wv, Wo, WTH);

    dim3 pgrid(1024, 1, 3);
    prep_inputs<<<pgrid, 256>>>(queries, keys, values, INH);

    dim3 qgrid(DM / GBN, MROWS / GBM, 3);
    gemm_qkv<<<qgrid, 256, SMEM_GEMMH>>>(INH, WTH, Qh, Kh, Vh);

    dim3 agrid(NQ / QROWS, NH, BATCH);
    attn_mma<<<agrid, 256, SMEM_ATT>>>(Qh, Kh, Vh, Oh);

    dim3 ogrid(DM / GBN, MROWS / GBM);
    gemm_out16<<<ogrid, 256, SMEM_GEMMH>>>(Oh, WTH + 3 * (size_t)DM * DM, bo, out);
}